// round 11
// baseline (speedup 1.0000x reference)
#include <cuda_runtime.h>
#include <stdint.h>

#define NCODE 1024
#define CDIM  256
#define NPIX  65536
#define HW    1024
#define BCHW  16777216
#define FLAG_CAP 65536
#define CAND_CAP 262144
#define GAP_THRESH 2.0e-3f

// ---------------- device scratch (no allocations allowed) ----------------
__device__ char  g_xq[(size_t)NPIX * CDIM];   // 16 MB int8
__device__ char  g_wq[NCODE * CDIM];
__device__ float g_sx[NPIX];
__device__ float g_sw[NCODE];
__device__ float g_wsq[NCODE];
__device__ float g_xsq[NPIX];
__device__ float g_bests[NPIX];
__device__ int   g_idx[NPIX];
__device__ unsigned long long g_key[NPIX];
__device__ int   g_flag_cnt;
__device__ int   g_flag_list[FLAG_CAP];
__device__ int   g_cand_cnt;
__device__ unsigned g_cand[CAND_CAP];

__device__ __forceinline__ uint32_t smem_u32(const void* p) {
    uint32_t a;
    asm("{ .reg .u64 t; cvta.to.shared.u64 t, %1; cvt.u32.u64 %0, t; }" : "=r"(a) : "l"(p));
    return a;
}

__device__ __forceinline__ unsigned long long packKey(float s, unsigned idx) {
    unsigned u = __float_as_uint(s);
    u = (u & 0x80000000u) ? ~u : (u | 0x80000000u);
    return (((unsigned long long)u) << 32) | (unsigned long long)idx;
}

__device__ __forceinline__ void cpasync16(uint32_t d, const void* s) {
    asm volatile("cp.async.ca.shared.global [%0], [%1], 16;" :: "r"(d), "l"(s) : "memory");
}

__device__ __forceinline__ void ldsm4(uint32_t* r, uint32_t addr) {
    asm volatile("ldmatrix.sync.aligned.m8n8.x4.shared.b16 {%0,%1,%2,%3}, [%4];"
                 : "=r"(r[0]), "=r"(r[1]), "=r"(r[2]), "=r"(r[3]) : "r"(addr));
}

__device__ __forceinline__ void mma_s8(int* c, const uint32_t* a, const uint32_t* b) {
    asm volatile(
        "mma.sync.aligned.m16n8k32.row.col.s32.s8.s8.s32 "
        "{%0,%1,%2,%3}, {%4,%5,%6,%7}, {%8,%9}, {%0,%1,%2,%3};"
        : "+r"(c[0]), "+r"(c[1]), "+r"(c[2]), "+r"(c[3])
        : "r"(a[0]), "r"(a[1]), "r"(a[2]), "r"(a[3]), "r"(b[0]), "r"(b[1]));
}

// The ONE approx-score expression: deterministic, used by vq_mma AND scan.
__device__ __forceinline__ float approx_score(int idot, float sx, float sw,
                                              float xsq, float wsq) {
    float d = __fmul_rn(__fmul_rn((float)idot, sx), sw);
    return __fadd_rn(__fsub_rn(xsq, __fmul_rn(2.0f, d)), wsq);
}

__device__ __forceinline__ int q8(float v, float inv) {
    int q = __float2int_rn(v * inv);
    return (q > 127) ? 127 : ((q < -127) ? -127 : q);
}

// ---------------- prep kernels ----------------
__global__ void prep_w(const float* __restrict__ w) {
    __shared__ float red[8];
    __shared__ float mred[8];
    __shared__ float bcast;
    int code = blockIdx.x, t = threadIdx.x;
    if (code == 0 && t == 0) { g_flag_cnt = 0; g_cand_cnt = 0; }
    float v = w[code * CDIM + t];
    float s = v * v, m = fabsf(v);
    #pragma unroll
    for (int o = 16; o > 0; o >>= 1) {
        s += __shfl_down_sync(0xffffffffu, s, o);
        m = fmaxf(m, __shfl_down_sync(0xffffffffu, m, o));
    }
    if ((t & 31) == 0) { red[t >> 5] = s; mred[t >> 5] = m; }
    __syncthreads();
    if (t == 0) {
        g_wsq[code] = ((red[0] + red[1]) + (red[2] + red[3])) +
                      ((red[4] + red[5]) + (red[6] + red[7]));
        float mm = fmaxf(fmaxf(fmaxf(mred[0], mred[1]), fmaxf(mred[2], mred[3])),
                         fmaxf(fmaxf(mred[4], mred[5]), fmaxf(mred[6], mred[7])));
        g_sw[code] = mm / 127.0f;
        bcast = (mm > 0.f) ? 127.0f / mm : 0.f;
    }
    __syncthreads();
    g_wq[code * CDIM + t] = (char)q8(v, bcast);
}

// x (B,C,H,W) f32 -> per-pixel int8 + scale + |x|^2 (xsq order preserved)
__global__ void prep_x(const float* __restrict__ x) {
    int p = blockIdx.x * 256 + threadIdx.x;
    const float* base = x + (size_t)(p >> 10) * (CDIM * HW) + (p & 1023);
    float s0 = 0.f, s1 = 0.f, s2 = 0.f, s3 = 0.f;
    float m = 0.f;
    #pragma unroll 4
    for (int c = 0; c < CDIM; c += 8) {
        float v[8];
        #pragma unroll
        for (int i = 0; i < 8; i++) v[i] = base[(c + i) * HW];
        s0 += v[0] * v[0]; s1 += v[1] * v[1]; s2 += v[2] * v[2]; s3 += v[3] * v[3];
        s0 += v[4] * v[4]; s1 += v[5] * v[5]; s2 += v[6] * v[6]; s3 += v[7] * v[7];
        #pragma unroll
        for (int i = 0; i < 8; i++) m = fmaxf(m, fabsf(v[i]));
    }
    g_xsq[p] = (s0 + s1) + (s2 + s3);
    g_sx[p] = m / 127.0f;
    float inv = (m > 0.f) ? 127.0f / m : 0.f;

    uint4* drow = (uint4*)(g_xq + (size_t)p * CDIM);
    #pragma unroll 2
    for (int c0 = 0; c0 < CDIM; c0 += 16) {
        uint32_t u[4];
        #pragma unroll
        for (int j = 0; j < 4; j++) {
            int q0 = q8(base[(c0 + 4 * j + 0) * HW], inv);
            int q1 = q8(base[(c0 + 4 * j + 1) * HW], inv);
            int q2 = q8(base[(c0 + 4 * j + 2) * HW], inv);
            int q3 = q8(base[(c0 + 4 * j + 3) * HW], inv);
            u[j] = (uint32_t)(q0 & 0xFF) | ((uint32_t)(q1 & 0xFF) << 8) |
                   ((uint32_t)(q2 & 0xFF) << 16) | ((uint32_t)(q3 & 0xFF) << 24);
        }
        drow[c0 >> 4] = make_uint4(u[0], u[1], u[2], u[3]);
    }
}

// W-tile stager (int8: 128 codes x 256B = 32KB), 256 threads
__device__ __forceinline__ void stage_wtile_at(uint32_t dstbase, int ct, int tid) {
    int r = tid >> 1, half = tid & 1;
    uint32_t dst = dstbase + (uint32_t)r * 256;
    uint32_t xm = (r & 7) << 4;
    const char* srow = g_wq + (size_t)(ct * 128 + r) * CDIM;
    #pragma unroll
    for (int j = 0; j < 8; j++) {
        uint32_t kb = half * 128 + j * 16;
        cpasync16(dst + (kb ^ xm), srow + kb);
    }
}

// 512-thread W-tile stager
__device__ __forceinline__ void stage_wtile512(uint32_t dstbase, int ct, int tid) {
    int r = tid >> 2, q = tid & 3;
    uint32_t dst = dstbase + (uint32_t)r * 256;
    uint32_t xm = (r & 7) << 4;
    const char* srow = g_wq + (size_t)(ct * 128 + r) * CDIM;
    #pragma unroll
    for (int j = 0; j < 4; j++) {
        uint32_t kb = q * 64 + j * 16;
        cpasync16(dst + (kb ^ xm), srow + kb);
    }
}

// ---------------- fused IMMA GEMM + top-2 argmin (128-px strips, 512 CTAs) ----
#define SM_X   0
#define SM_W   32768
#define SM_RED 98304
#define SM_TOT (98304 + 6144)

__global__ __launch_bounds__(512, 1) void vq_mma() {
    extern __shared__ char smem[];
    uint32_t sb = smem_u32(smem);
    const int tid = threadIdx.x, l = tid & 31, wid = tid >> 5;
    const int mw = wid & 3;        // code-warp: 4 x 32 codes
    const int nw = wid >> 2;       // pixel-warp: 4 x 32 pixels
    const int row0 = blockIdx.x * 128;
    float* s1sh = (float*)(smem + SM_RED);
    int*   i1sh = (int*)(smem + SM_RED + 2048);
    float* s2sh = (float*)(smem + SM_RED + 4096);

    // Stage resident X strip: 128 rows x 256B, swizzled
    {
        int r = tid >> 2, q = tid & 3;
        const char* srow = g_xq + (size_t)(row0 + r) * CDIM;
        uint32_t dx = sb + SM_X + (uint32_t)r * 256;
        uint32_t xm = (r & 7) << 4;
        #pragma unroll
        for (int j = 0; j < 4; j++) {
            uint32_t kb = q * 64 + j * 16;
            cpasync16(dx + (kb ^ xm), srow + kb);
        }
    }
    stage_wtile512(sb + SM_W, 0, tid);
    asm volatile("cp.async.commit_group;" ::: "memory");
    stage_wtile512(sb + SM_W + 32768, 1, tid);
    asm volatile("cp.async.commit_group;" ::: "memory");

    float xsqr[8], sxr[8];
    #pragma unroll
    for (int s = 0; s < 8; s++) {
        int px = nw * 32 + (s >> 1) * 8 + (l & 3) * 2 + (s & 1);
        xsqr[s] = g_xsq[row0 + px];
        sxr[s] = g_sx[row0 + px];
    }

    uint32_t a_row[2], a_x[2];
    #pragma unroll
    for (int tm = 0; tm < 2; tm++) {
        int rA = mw * 32 + tm * 16 + (l & 15);
        a_row[tm] = rA * 256;
        a_x[tm] = (rA & 7) << 4;
    }
    const uint32_t off16a = (l >> 4) * 16;
    uint32_t b_row[2], b_x[2];
    #pragma unroll
    for (int tp = 0; tp < 2; tp++) {
        int rB = nw * 32 + tp * 16 + (l & 7) + ((l >> 4) << 3);
        b_row[tp] = rB * 256;
        b_x[tp] = (rB & 7) << 4;
    }
    const uint32_t off16b = ((l >> 3) & 1) * 16;

    int acc[2][4][4];
    #pragma unroll
    for (int i = 0; i < 2; i++)
        #pragma unroll
        for (int j = 0; j < 4; j++)
            #pragma unroll
            for (int k = 0; k < 4; k++) acc[i][j][k] = 0;

    float best_s[8], sec_s[8];
    int best_i[8];
    #pragma unroll
    for (int s = 0; s < 8; s++) { best_s[s] = 3.4e38f; sec_s[s] = 3.4e38f; best_i[s] = 0; }

    for (int ct = 0; ct < 8; ct++) {
        if (ct < 7) asm volatile("cp.async.wait_group 1;" ::: "memory");
        else        asm volatile("cp.async.wait_group 0;" ::: "memory");
        __syncthreads();

        uint32_t bufw = sb + SM_W + (uint32_t)(ct & 1) * 32768;
        #pragma unroll
        for (int kk = 0; kk < 8; kk++) {    // k32 int8 per step: 8 steps cover 256
            uint32_t a0[4], a1[4];
            uint32_t ca = kk * 32 + off16a;
            ldsm4(a0, bufw + a_row[0] + (ca ^ a_x[0]));
            ldsm4(a1, bufw + a_row[1] + (ca ^ a_x[1]));
            uint32_t kb = kk * 32 + off16b;
            #pragma unroll
            for (int tp = 0; tp < 2; tp++) {
                uint32_t b[4];
                ldsm4(b, sb + SM_X + b_row[tp] + (kb ^ b_x[tp]));
                mma_s8(acc[0][2 * tp],     a0, b);
                mma_s8(acc[0][2 * tp + 1], a0, b + 2);
                mma_s8(acc[1][2 * tp],     a1, b);
                mma_s8(acc[1][2 * tp + 1], a1, b + 2);
            }
        }
        __syncthreads();   // all warps done reading bufw before restage
        if (ct + 2 < 8) {
            stage_wtile512(sb + SM_W + (uint32_t)(ct & 1) * 32768, ct + 2, tid);
            asm volatile("cp.async.commit_group;" ::: "memory");
        }

        // Fold this code tile into running top-2
        {
            int cb = ct * 128 + mw * 32 + (l >> 2);
            float wq0 = __ldg(&g_wsq[cb]),      sw0 = __ldg(&g_sw[cb]);
            float wq1 = __ldg(&g_wsq[cb + 8]),  sw1 = __ldg(&g_sw[cb + 8]);
            float wq2 = __ldg(&g_wsq[cb + 16]), sw2 = __ldg(&g_sw[cb + 16]);
            float wq3 = __ldg(&g_wsq[cb + 24]), sw3 = __ldg(&g_sw[cb + 24]);
            #pragma unroll
            for (int tm = 0; tm < 2; tm++) {
                float wlo_ = tm ? wq2 : wq0, slo_ = tm ? sw2 : sw0;
                float whi_ = tm ? wq3 : wq1, shi_ = tm ? sw3 : sw1;
                int c_lo = cb + tm * 16, c_hi = cb + tm * 16 + 8;
                #pragma unroll
                for (int tn = 0; tn < 4; tn++) {
                    #pragma unroll
                    for (int rg = 0; rg < 4; rg++) {
                        int slot = tn * 2 + (rg & 1);
                        float wq = (rg >> 1) ? whi_ : wlo_;
                        float sw = (rg >> 1) ? shi_ : slo_;
                        int code = (rg >> 1) ? c_hi : c_lo;
                        float s = approx_score(acc[tm][tn][rg], sxr[slot], sw,
                                               xsqr[slot], wq);
                        if (s < best_s[slot]) {
                            sec_s[slot] = best_s[slot];
                            best_s[slot] = s; best_i[slot] = code;
                        } else if (s < sec_s[slot]) {
                            sec_s[slot] = s;
                        }
                        acc[tm][tn][rg] = 0;
                    }
                }
            }
        }
    }

    // Cross-lane top-2 merge
    #pragma unroll
    for (int s = 0; s < 8; s++) {
        float bs = best_s[s], ss = sec_s[s];
        int bi = best_i[s];
        #pragma unroll
        for (int off = 4; off <= 16; off <<= 1) {
            float ob = __shfl_xor_sync(0xffffffffu, bs, off);
            int   oi = __shfl_xor_sync(0xffffffffu, bi, off);
            float os = __shfl_xor_sync(0xffffffffu, ss, off);
            bool take = (ob < bs) || (ob == bs && oi < bi);
            float losing = take ? bs : ob;
            if (take) { bs = ob; bi = oi; }
            ss = fminf(fminf(ss, os), losing);
        }
        if ((l >> 2) == 0) {
            int px = nw * 32 + (s >> 1) * 8 + (l & 3) * 2 + (s & 1);
            s1sh[mw * 128 + px] = bs;
            i1sh[mw * 128 + px] = bi;
            s2sh[mw * 128 + px] = ss;
        }
    }
    __syncthreads();

    // Cross-warp merge (4 code-warps per pixel); flag near-ties for rescue
    if (tid < 128) {
        float bs = s1sh[tid]; int bi = i1sh[tid]; float ss = s2sh[tid];
        #pragma unroll
        for (int wv = 1; wv < 4; wv++) {
            float ob = s1sh[wv * 128 + tid];
            int   oi = i1sh[wv * 128 + tid];
            float os = s2sh[wv * 128 + tid];
            bool take = (ob < bs) || (ob == bs && oi < bi);
            float losing = take ? bs : ob;
            if (take) { bs = ob; bi = oi; }
            ss = fminf(fminf(ss, os), losing);
        }
        int p = row0 + tid;
        g_bests[p] = bs;
        if (ss - bs < GAP_THRESH) {
            int slot = atomicAdd(&g_flag_cnt, 1);
            if (slot < FLAG_CAP) {
                g_flag_list[slot] = p;
                g_key[p] = ~0ull;
                g_idx[p] = -1;        // gather resolves from g_key
            } else {
                g_idx[p] = bi;
            }
        } else {
            g_idx[p] = bi;
        }
    }
}

// ---------------- rescue scan: int8 rescore flagged px, emit candidates ----
// smem: XS 32KB | W 32KB | pxid 512B
#define SC_X   0
#define SC_W   32768
#define SC_PX  65536
#define SC_TOT (65536 + 512)

__global__ __launch_bounds__(256) void rescue_scan() {
    extern __shared__ char smem[];
    uint32_t sb = smem_u32(smem);
    const int tid = threadIdx.x, l = tid & 31, wid = tid >> 5;
    const int mw = wid & 3, nw = wid >> 2;
    const int split = blockIdx.x & 7;        // code tile (one of 8)
    const int gslot = blockIdx.x >> 3;       // group slot (64)
    int* pxid = (int*)(smem + SC_PX);

    int nflag = g_flag_cnt;
    if (nflag > FLAG_CAP) nflag = FLAG_CAP;
    int ngroups = (nflag + 127) >> 7;
    if (gslot >= ngroups) return;

    stage_wtile_at(sb + SC_W, split, tid);
    asm volatile("cp.async.commit_group;" ::: "memory");

    uint32_t a_row[2], a_x[2];
    #pragma unroll
    for (int tm = 0; tm < 2; tm++) {
        int rA = mw * 32 + tm * 16 + (l & 15);
        a_row[tm] = rA * 256;
        a_x[tm] = (rA & 7) << 4;
    }
    const uint32_t off16a = (l >> 4) * 16;
    uint32_t b_row[4], b_x[4];
    #pragma unroll
    for (int tp = 0; tp < 4; tp++) {
        int rB = nw * 64 + tp * 16 + (l & 7) + ((l >> 4) << 3);
        b_row[tp] = rB * 256;
        b_x[tp] = (rB & 7) << 4;
    }
    const uint32_t off16b = ((l >> 3) & 1) * 16;

    int acc[2][8][4];
    #pragma unroll
    for (int i = 0; i < 2; i++)
        #pragma unroll
        for (int j = 0; j < 8; j++)
            #pragma unroll
            for (int k = 0; k < 4; k++) acc[i][j][k] = 0;

    for (int grp = gslot; grp < ngroups; grp += 64) {
        int base = grp * 128;
        __syncthreads();     // previous group done with XS
        if (tid < 128) {
            int fi = base + tid;
            pxid[tid] = g_flag_list[(fi < nflag) ? fi : (nflag - 1)];
        }
        __syncthreads();

        // Gather flagged pixels' int8 rows (same swizzle as vq_mma)
        {
            int r = tid >> 1, half = tid & 1;
            const char* srow = g_xq + (size_t)pxid[r] * CDIM;
            uint32_t dx = sb + SC_X + (uint32_t)r * 256;
            uint32_t xm = (r & 7) << 4;
            #pragma unroll
            for (int j = 0; j < 8; j++) {
                uint32_t kb = half * 128 + j * 16;
                cpasync16(dx + (kb ^ xm), srow + kb);
            }
        }
        asm volatile("cp.async.commit_group;" ::: "memory");

        float xsqr[16], lims[16], sxs[16];
        int pxs[16];
        #pragma unroll
        for (int s = 0; s < 16; s++) {
            int r = nw * 64 + (s >> 1) * 8 + (l & 3) * 2 + (s & 1);
            int p = pxid[r];
            pxs[s] = p;
            xsqr[s] = g_xsq[p];
            sxs[s] = g_sx[p];
            lims[s] = g_bests[p] + GAP_THRESH;
        }

        asm volatile("cp.async.wait_group 0;" ::: "memory");
        __syncthreads();

        uint32_t bufw = sb + SC_W;
        #pragma unroll
        for (int kk = 0; kk < 8; kk++) {
            uint32_t a0[4], a1[4];
            uint32_t ca = kk * 32 + off16a;
            ldsm4(a0, bufw + a_row[0] + (ca ^ a_x[0]));
            ldsm4(a1, bufw + a_row[1] + (ca ^ a_x[1]));
            uint32_t kb = kk * 32 + off16b;
            #pragma unroll
            for (int tp = 0; tp < 4; tp++) {
                uint32_t b[4];
                ldsm4(b, sb + SC_X + b_row[tp] + (kb ^ b_x[tp]));
                mma_s8(acc[0][2 * tp],     a0, b);
                mma_s8(acc[0][2 * tp + 1], a0, b + 2);
                mma_s8(acc[1][2 * tp],     a1, b);
                mma_s8(acc[1][2 * tp + 1], a1, b + 2);
            }
        }

        int cb = split * 128 + mw * 32 + (l >> 2);
        float wq0 = __ldg(&g_wsq[cb]),      sw0 = __ldg(&g_sw[cb]);
        float wq1 = __ldg(&g_wsq[cb + 8]),  sw1 = __ldg(&g_sw[cb + 8]);
        float wq2 = __ldg(&g_wsq[cb + 16]), sw2 = __ldg(&g_sw[cb + 16]);
        float wq3 = __ldg(&g_wsq[cb + 24]), sw3 = __ldg(&g_sw[cb + 24]);
        #pragma unroll
        for (int tm = 0; tm < 2; tm++) {
            float wlo_ = tm ? wq2 : wq0, slo_ = tm ? sw2 : sw0;
            float whi_ = tm ? wq3 : wq1, shi_ = tm ? sw3 : sw1;
            int c_lo = cb + tm * 16, c_hi = cb + tm * 16 + 8;
            #pragma unroll
            for (int tn = 0; tn < 8; tn++) {
                #pragma unroll
                for (int rg = 0; rg < 4; rg++) {
                    int slot = tn * 2 + (rg & 1);
                    float wq = (rg >> 1) ? whi_ : wlo_;
                    float sw = (rg >> 1) ? shi_ : slo_;
                    int code = (rg >> 1) ? c_hi : c_lo;
                    float s = approx_score(acc[tm][tn][rg], sxs[slot], sw,
                                           xsqr[slot], wq);
                    if (s < lims[slot]) {
                        int ci = atomicAdd(&g_cand_cnt, 1);
                        if (ci < CAND_CAP)
                            g_cand[ci] = ((unsigned)pxs[slot] << 16) | (unsigned)code;
                    }
                    acc[tm][tn][rg] = 0;
                }
            }
        }
    }
}

// ---------------- exact fp32 scoring of candidates (1 warp each) ----------------
__global__ __launch_bounds__(256) void rescue_exact(const float* __restrict__ x,
                                                    const float* __restrict__ w) {
    const int l = threadIdx.x & 31, wid = threadIdx.x >> 5;
    int total = g_cand_cnt;
    if (total > CAND_CAP) total = CAND_CAP;
    for (int ci = blockIdx.x * 8 + wid; ci < total; ci += gridDim.x * 8) {
        unsigned pc = g_cand[ci];
        int px = pc >> 16, code = pc & 0xFFFF;
        const float* xb = x + (size_t)(px >> 10) * (CDIM * HW) + (px & 1023);
        const float* wr = w + (size_t)code * CDIM;
        float dot = 0.f;
        #pragma unroll
        for (int j = 0; j < 8; j++) {
            int c = l + j * 32;
            dot = fmaf(__ldg(&xb[(size_t)c * HW]), __ldg(&wr[c]), dot);
        }
        #pragma unroll
        for (int o = 16; o > 0; o >>= 1) dot += __shfl_down_sync(0xffffffffu, dot, o);
        if (l == 0) {
            float s = __fadd_rn(__fsub_rn(g_xsq[px], __fmul_rn(2.0f, dot)),
                                __ldg(&g_wsq[code]));
            atomicMin(&g_key[px], packKey(s, (unsigned)code));
        }
    }
}

// ---------------- gather + write outputs (resolves rescued pixels inline) ----
__global__ __launch_bounds__(256) void gather_kernel(const float* __restrict__ w,
                                                     float* __restrict__ out) {
    __shared__ float wsh[32][257];
    __shared__ int idxsh[32];

    const int bh = blockIdx.x;
    const int b  = bh >> 5;
    const int h  = bh & 31;
    const int p0 = bh * 32;
    const int tid = threadIdx.x;

    if (tid < 32) {
        int idx = g_idx[p0 + tid];
        if (idx < 0) idx = (int)(g_key[p0 + tid] & 0xFFFFFFFFULL);
        idxsh[tid] = idx;
        out[2 * BCHW + p0 + tid] = (float)idx;
    }
    __syncthreads();

    for (int j = tid; j < 32 * CDIM; j += 256) {
        int wl = j >> 8, c = j & 255;
        wsh[wl][c] = w[(size_t)idxsh[wl] * CDIM + c];
    }
    __syncthreads();

    const int qbase = b * (CDIM * HW) + h * 32;
    for (int j = tid; j < 32 * CDIM; j += 256) {
        int c = j >> 5, ww = j & 31;
        float v = wsh[ww][c];
        int addr = qbase + c * HW + ww;
        out[addr] = v;
        out[addr + BCHW] = v;
    }
}

extern "C" void kernel_launch(void* const* d_in, const int* in_sizes, int n_in,
                              void* d_out, int out_size) {
    const float* x = (const float*)d_in[0];   // (64, 256, 32, 32) f32
    const float* w = (const float*)d_in[1];   // (1024, 256) f32
    float* out = (float*)d_out;

    cudaFuncSetAttribute(vq_mma, cudaFuncAttributeMaxDynamicSharedMemorySize, SM_TOT);
    cudaFuncSetAttribute(rescue_scan, cudaFuncAttributeMaxDynamicSharedMemorySize, SC_TOT);

    prep_w<<<NCODE, 256>>>(w);
    prep_x<<<NPIX / 256, 256>>>(x);
    vq_mma<<<NPIX / 128, 512, SM_TOT>>>();
    rescue_scan<<<512, 256, SC_TOT>>>();
    rescue_exact<<<256, 256>>>(x, w);
    gather_kernel<<<NPIX / 32, 256>>>(w, out);
}

// round 12
// speedup vs baseline: 1.6640x; 1.6640x over previous
#include <cuda_runtime.h>
#include <cuda_fp16.h>
#include <stdint.h>

#define NCODE 1024
#define CDIM  256
#define NPIX  65536
#define HW    1024
#define BCHW  16777216
#define FLAG_CAP 32768
#define CAND_CAP 131072
#define GAP_THRESH 2.0e-4f

// ---------------- device scratch (no allocations allowed) ----------------
__device__ __half g_xhi[(size_t)NPIX * CDIM];   // 32 MB
__device__ __half g_whi[NCODE * CDIM];
__device__ float g_wsq[NCODE];
__device__ float g_xsq[NPIX];
__device__ float g_bests[NPIX];
__device__ int   g_idx[NPIX];
__device__ unsigned long long g_key[NPIX];
__device__ int   g_flag_cnt;
__device__ int   g_flag_list[FLAG_CAP];
__device__ int   g_cand_cnt;
__device__ unsigned g_cand[CAND_CAP];

__device__ __forceinline__ uint32_t smem_u32(const void* p) {
    uint32_t a;
    asm("{ .reg .u64 t; cvta.to.shared.u64 t, %1; cvt.u32.u64 %0, t; }" : "=r"(a) : "l"(p));
    return a;
}

__device__ __forceinline__ unsigned long long packKey(float s, unsigned idx) {
    unsigned u = __float_as_uint(s);
    u = (u & 0x80000000u) ? ~u : (u | 0x80000000u);
    return (((unsigned long long)u) << 32) | (unsigned long long)idx;
}

__device__ __forceinline__ void cpasync16(uint32_t d, const void* s) {
    asm volatile("cp.async.ca.shared.global [%0], [%1], 16;" :: "r"(d), "l"(s) : "memory");
}

__device__ __forceinline__ void ldsm4(uint32_t* r, uint32_t addr) {
    asm volatile("ldmatrix.sync.aligned.m8n8.x4.shared.b16 {%0,%1,%2,%3}, [%4];"
                 : "=r"(r[0]), "=r"(r[1]), "=r"(r[2]), "=r"(r[3]) : "r"(addr));
}

__device__ __forceinline__ void mma_f16(float* c, const uint32_t* a, const uint32_t* b) {
    asm volatile(
        "mma.sync.aligned.m16n8k16.row.col.f32.f16.f16.f32 "
        "{%0,%1,%2,%3}, {%4,%5,%6,%7}, {%8,%9}, {%0,%1,%2,%3};"
        : "+f"(c[0]), "+f"(c[1]), "+f"(c[2]), "+f"(c[3])
        : "r"(a[0]), "r"(a[1]), "r"(a[2]), "r"(a[3]), "r"(b[0]), "r"(b[1]));
}

// ---------------- prep kernels (identical to R10) ----------------
__global__ void prep_w(const float* __restrict__ w) {
    __shared__ float red[8];
    int code = blockIdx.x, t = threadIdx.x;
    if (code == 0 && t == 0) { g_flag_cnt = 0; g_cand_cnt = 0; }
    float v = w[code * CDIM + t];
    g_whi[code * CDIM + t] = __float2half(v);
    float s = v * v;
    #pragma unroll
    for (int o = 16; o > 0; o >>= 1) s += __shfl_down_sync(0xffffffffu, s, o);
    if ((t & 31) == 0) red[t >> 5] = s;
    __syncthreads();
    if (t == 0) {
        g_wsq[code] = ((red[0] + red[1]) + (red[2] + red[3])) +
                      ((red[4] + red[5]) + (red[6] + red[7]));
    }
}

__global__ void prep_x(const float* __restrict__ x) {
    int p = blockIdx.x * 256 + threadIdx.x;
    const float* base = x + (size_t)(p >> 10) * (CDIM * HW) + (p & 1023);
    float s0 = 0.f, s1 = 0.f, s2 = 0.f, s3 = 0.f;
    uint4* dhi = (uint4*)(g_xhi + (size_t)p * CDIM);
    #pragma unroll 4
    for (int c = 0; c < CDIM; c += 8) {
        float v[8];
        #pragma unroll
        for (int i = 0; i < 8; i++) v[i] = base[(c + i) * HW];
        s0 += v[0] * v[0]; s1 += v[1] * v[1]; s2 += v[2] * v[2]; s3 += v[3] * v[3];
        s0 += v[4] * v[4]; s1 += v[5] * v[5]; s2 += v[6] * v[6]; s3 += v[7] * v[7];
        uint32_t hw_[4];
        #pragma unroll
        for (int i = 0; i < 4; i++) {
            __half2 h2 = __floats2half2_rn(v[2 * i], v[2 * i + 1]);
            hw_[i] = *(uint32_t*)&h2;
        }
        dhi[c >> 3] = make_uint4(hw_[0], hw_[1], hw_[2], hw_[3]);
    }
    g_xsq[p] = (s0 + s1) + (s2 + s3);
}

// 128-code W-tile stager (64KB), 256 threads — used by rescue_scan
__device__ __forceinline__ void stage_wtile_at(uint32_t dstbase, int ct, int tid) {
    int r = tid >> 1, half = tid & 1;
    uint32_t dst = dstbase + (uint32_t)r * 512;
    uint32_t xm = (r & 7) << 4;
    const char* srow = (const char*)(g_whi + (size_t)(ct * 128 + r) * CDIM);
    #pragma unroll
    for (int j = 0; j < 16; j++) {
        uint32_t kb = half * 256 + j * 16;
        cpasync16(dst + (kb ^ xm), srow + kb);
    }
}

// 64-code W-tile stager (32KB), 256 threads — used by vq_mma
__device__ __forceinline__ void stage_wtile64(uint32_t dstbase, int ct, int tid) {
    int r = tid >> 2, q = tid & 3;
    uint32_t dst = dstbase + (uint32_t)r * 512;
    uint32_t xm = (r & 7) << 4;
    const char* srow = (const char*)(g_whi + (size_t)(ct * 64 + r) * CDIM);
    #pragma unroll
    for (int j = 0; j < 8; j++) {
        uint32_t kb = q * 128 + j * 16;
        cpasync16(dst + (kb ^ xm), srow + kb);
    }
}

// ---------------- fused HMMA GEMM + top-2 argmin (64-px strips, occ 2) ----
// smem: X 32KB | W 2x32KB | red 3KB
#define SM_X   0
#define SM_W   32768
#define SM_RED 98304
#define SM_TOT (98304 + 3072)

__global__ __launch_bounds__(256, 2) void vq_mma() {
    extern __shared__ char smem[];
    uint32_t sb = smem_u32(smem);
    const int tid = threadIdx.x, l = tid & 31, wid = tid >> 5;
    const int cw = wid & 3;        // code-warp: 4 x 16 codes
    const int pw = wid >> 2;       // pixel-warp: 2 x 32 pixels
    const int row0 = blockIdx.x * 64;
    float* s1sh = (float*)(smem + SM_RED);
    int*   i1sh = (int*)(smem + SM_RED + 1024);
    float* s2sh = (float*)(smem + SM_RED + 2048);

    // Stage resident X strip: 64 rows x 512B, swizzled
    {
        int r = tid >> 2, q = tid & 3;
        const char* shi = (const char*)(g_xhi + (size_t)(row0 + r) * CDIM);
        uint32_t dx = sb + SM_X + (uint32_t)r * 512;
        uint32_t xm = (r & 7) << 4;
        #pragma unroll
        for (int j = 0; j < 8; j++) {
            uint32_t kb = q * 128 + j * 16;
            cpasync16(dx + (kb ^ xm), shi + kb);
        }
    }
    stage_wtile64(sb + SM_W, 0, tid);
    asm volatile("cp.async.commit_group;" ::: "memory");
    stage_wtile64(sb + SM_W + 32768, 1, tid);
    asm volatile("cp.async.commit_group;" ::: "memory");

    // 8 pixel slots per lane: px = pw*32 + (s>>1)*8 + (l&3)*2 + (s&1)
    float xsqr[8];
    #pragma unroll
    for (int s = 0; s < 8; s++) {
        int px = pw * 32 + (s >> 1) * 8 + (l & 3) * 2 + (s & 1);
        xsqr[s] = g_xsq[row0 + px];
    }

    // A (codes): 16 rows per warp
    const int rA = cw * 16 + (l & 15);
    const uint32_t a_row = rA * 512;
    const uint32_t a_x = (rA & 7) << 4;
    const uint32_t off16a = (l >> 4) * 16;
    // B (pixels): 2 x 16-px fragments
    uint32_t b_row[2], b_x[2];
    #pragma unroll
    for (int tp = 0; tp < 2; tp++) {
        int rB = pw * 32 + tp * 16 + (l & 7) + ((l >> 4) << 3);
        b_row[tp] = rB * 512;
        b_x[tp] = (rB & 7) << 4;
    }
    const uint32_t off16b = ((l >> 3) & 1) * 16;

    float acc[4][4];
    #pragma unroll
    for (int j = 0; j < 4; j++)
        #pragma unroll
        for (int k = 0; k < 4; k++) acc[j][k] = 0.f;

    float best_s[8], sec_s[8];
    int best_i[8];
    #pragma unroll
    for (int s = 0; s < 8; s++) { best_s[s] = 3.4e38f; sec_s[s] = 3.4e38f; best_i[s] = 0; }

    for (int ct = 0; ct < 16; ct++) {
        if (ct < 15) asm volatile("cp.async.wait_group 1;" ::: "memory");
        else         asm volatile("cp.async.wait_group 0;" ::: "memory");
        __syncthreads();

        uint32_t bufw = sb + SM_W + (uint32_t)(ct & 1) * 32768;
        #pragma unroll 4
        for (int kk = 0; kk < 16; kk++) {
            uint32_t a[4];
            ldsm4(a, bufw + a_row + ((kk * 32 + off16a) ^ a_x));
            uint32_t kb = kk * 32 + off16b;
            #pragma unroll
            for (int tp = 0; tp < 2; tp++) {
                uint32_t b[4];
                ldsm4(b, sb + SM_X + b_row[tp] + (kb ^ b_x[tp]));
                mma_f16(acc[2 * tp],     a, b);
                mma_f16(acc[2 * tp + 1], a, b + 2);
            }
        }
        __syncthreads();   // all warps done reading bufw before restage
        if (ct + 2 < 16) {
            stage_wtile64(sb + SM_W + (uint32_t)(ct & 1) * 32768, ct + 2, tid);
            asm volatile("cp.async.commit_group;" ::: "memory");
        }

        // Fold this 64-code tile into running top-2
        {
            int cb = ct * 64 + cw * 16 + (l >> 2);
            float wqlo = __ldg(&g_wsq[cb]);
            float wqhi = __ldg(&g_wsq[cb + 8]);
            #pragma unroll
            for (int j = 0; j < 4; j++) {
                #pragma unroll
                for (int rg = 0; rg < 4; rg++) {
                    int slot = j * 2 + (rg & 1);
                    float dot = acc[j][rg];
                    float wq = (rg >> 1) ? wqhi : wqlo;
                    int code = (rg >> 1) ? cb + 8 : cb;
                    float s = __fadd_rn(__fsub_rn(xsqr[slot],
                                                  __fmul_rn(2.0f, dot)), wq);
                    if (s < best_s[slot]) {
                        sec_s[slot] = best_s[slot];
                        best_s[slot] = s; best_i[slot] = code;
                    } else if (s < sec_s[slot]) {
                        sec_s[slot] = s;
                    }
                    acc[j][rg] = 0.f;
                }
            }
        }
    }

    // Cross-lane top-2 merge (8 lanes share a pixel slot set)
    #pragma unroll
    for (int s = 0; s < 8; s++) {
        float bs = best_s[s], ss = sec_s[s];
        int bi = best_i[s];
        #pragma unroll
        for (int off = 4; off <= 16; off <<= 1) {
            float ob = __shfl_xor_sync(0xffffffffu, bs, off);
            int   oi = __shfl_xor_sync(0xffffffffu, bi, off);
            float os = __shfl_xor_sync(0xffffffffu, ss, off);
            bool take = (ob < bs) || (ob == bs && oi < bi);
            float losing = take ? bs : ob;
            if (take) { bs = ob; bi = oi; }
            ss = fminf(fminf(ss, os), losing);
        }
        if ((l >> 2) == 0) {
            int px = pw * 32 + (s >> 1) * 8 + (l & 3) * 2 + (s & 1);
            s1sh[cw * 64 + px] = bs;
            i1sh[cw * 64 + px] = bi;
            s2sh[cw * 64 + px] = ss;
        }
    }
    __syncthreads();

    // Cross-warp merge (4 code-warps per pixel); flag near-ties for rescue
    if (tid < 64) {
        float bs = s1sh[tid]; int bi = i1sh[tid]; float ss = s2sh[tid];
        #pragma unroll
        for (int wv = 1; wv < 4; wv++) {
            float ob = s1sh[wv * 64 + tid];
            int   oi = i1sh[wv * 64 + tid];
            float os = s2sh[wv * 64 + tid];
            bool take = (ob < bs) || (ob == bs && oi < bi);
            float losing = take ? bs : ob;
            if (take) { bs = ob; bi = oi; }
            ss = fminf(fminf(ss, os), losing);
        }
        int p = row0 + tid;
        g_bests[p] = bs;
        if (ss - bs < GAP_THRESH) {
            int slot = atomicAdd(&g_flag_cnt, 1);
            if (slot < FLAG_CAP) {
                g_flag_list[slot] = p;
                g_key[p] = ~0ull;
                g_idx[p] = -1;        // gather resolves from g_key
            } else {
                g_idx[p] = bi;
            }
        } else {
            g_idx[p] = bi;
        }
    }
}

// ---------------- rescue scan (identical to R10) ----------------
// smem: XS 64KB | W 64KB (single) | pxid 512B
#define SC_X   0
#define SC_W   65536
#define SC_PX  131072
#define SC_TOT (131072 + 512)

__global__ __launch_bounds__(256, 1) void rescue_scan() {
    extern __shared__ char smem[];
    uint32_t sb = smem_u32(smem);
    const int tid = threadIdx.x, l = tid & 31, wid = tid >> 5;
    const int mw = wid & 3, nw = wid >> 2;
    const int split = blockIdx.x & 7;        // code tile (one of 8)
    const int gslot = blockIdx.x >> 3;       // group slot (64)
    int* pxid = (int*)(smem + SC_PX);

    int nflag = g_flag_cnt;
    if (nflag > FLAG_CAP) nflag = FLAG_CAP;
    int ngroups = (nflag + 127) >> 7;
    if (gslot >= ngroups) return;

    stage_wtile_at(sb + SC_W, split, tid);
    asm volatile("cp.async.commit_group;" ::: "memory");

    uint32_t a_row[2], a_x[2];
    #pragma unroll
    for (int tm = 0; tm < 2; tm++) {
        int rA = mw * 32 + tm * 16 + (l & 15);
        a_row[tm] = rA * 512;
        a_x[tm] = (rA & 7) << 4;
    }
    const uint32_t off16a = (l >> 4) * 16;
    uint32_t b_row[4], b_x[4];
    #pragma unroll
    for (int tp = 0; tp < 4; tp++) {
        int rB = nw * 64 + tp * 16 + (l & 7) + ((l >> 4) << 3);
        b_row[tp] = rB * 512;
        b_x[tp] = (rB & 7) << 4;
    }
    const uint32_t off16b = ((l >> 3) & 1) * 16;

    float acc[2][8][4];
    #pragma unroll
    for (int i = 0; i < 2; i++)
        #pragma unroll
        for (int j = 0; j < 8; j++)
            #pragma unroll
            for (int k = 0; k < 4; k++) acc[i][j][k] = 0.f;

    for (int grp = gslot; grp < ngroups; grp += 64) {
        int base = grp * 128;
        __syncthreads();     // previous group done with XS
        if (tid < 128) {
            int fi = base + tid;
            pxid[tid] = g_flag_list[(fi < nflag) ? fi : (nflag - 1)];
        }
        __syncthreads();

        {
            int r = tid >> 1, half = tid & 1;
            const char* shi = (const char*)(g_xhi + (size_t)pxid[r] * CDIM);
            uint32_t dx = sb + SC_X + (uint32_t)r * 512;
            uint32_t xm = (r & 7) << 4;
            #pragma unroll
            for (int j = 0; j < 16; j++) {
                uint32_t kb = half * 256 + j * 16;
                cpasync16(dx + (kb ^ xm), shi + kb);
            }
        }
        asm volatile("cp.async.commit_group;" ::: "memory");

        float xsqr[16], lims[16];
        int pxs[16];
        #pragma unroll
        for (int s = 0; s < 16; s++) {
            int r = nw * 64 + (s >> 1) * 8 + (l & 3) * 2 + (s & 1);
            int p = pxid[r];
            pxs[s] = p;
            xsqr[s] = g_xsq[p];
            lims[s] = g_bests[p] + GAP_THRESH;
        }

        asm volatile("cp.async.wait_group 0;" ::: "memory");
        __syncthreads();

        uint32_t bufw = sb + SC_W;
        #pragma unroll 4
        for (int kk = 0; kk < 16; kk++) {
            uint32_t a0[4], a1[4];
            uint32_t ca = kk * 32 + off16a;
            ldsm4(a0, bufw + a_row[0] + (ca ^ a_x[0]));
            ldsm4(a1, bufw + a_row[1] + (ca ^ a_x[1]));
            uint32_t kb = kk * 32 + off16b;
            #pragma unroll
            for (int tp = 0; tp < 4; tp++) {
                uint32_t b[4];
                ldsm4(b, sb + SC_X + b_row[tp] + (kb ^ b_x[tp]));
                mma_f16(acc[0][2 * tp],     a0, b);
                mma_f16(acc[0][2 * tp + 1], a0, b + 2);
                mma_f16(acc[1][2 * tp],     a1, b);
                mma_f16(acc[1][2 * tp + 1], a1, b + 2);
            }
        }

        int cb = split * 128 + mw * 32 + (l >> 2);
        float wq0 = __ldg(&g_wsq[cb]);
        float wq1 = __ldg(&g_wsq[cb + 8]);
        float wq2 = __ldg(&g_wsq[cb + 16]);
        float wq3 = __ldg(&g_wsq[cb + 24]);
        #pragma unroll
        for (int tm = 0; tm < 2; tm++) {
            float wlo_ = tm ? wq2 : wq0;
            float whi_ = tm ? wq3 : wq1;
            int c_lo = cb + tm * 16, c_hi = cb + tm * 16 + 8;
            #pragma unroll
            for (int tn = 0; tn < 8; tn++) {
                #pragma unroll
                for (int rg = 0; rg < 4; rg++) {
                    int slot = tn * 2 + (rg & 1);
                    float dot = acc[tm][tn][rg];
                    float wq = (rg >> 1) ? whi_ : wlo_;
                    int code = (rg >> 1) ? c_hi : c_lo;
                    float s = __fadd_rn(__fsub_rn(xsqr[slot],
                                                  __fmul_rn(2.0f, dot)), wq);
                    if (s < lims[slot]) {
                        int ci = atomicAdd(&g_cand_cnt, 1);
                        if (ci < CAND_CAP)
                            g_cand[ci] = ((unsigned)pxs[slot] << 16) | (unsigned)code;
                    }
                    acc[tm][tn][rg] = 0.f;
                }
            }
        }
    }
}

// ---------------- exact fp32 scoring of candidates (1 warp each) ----------------
__global__ __launch_bounds__(256) void rescue_exact(const float* __restrict__ x,
                                                    const float* __restrict__ w) {
    const int l = threadIdx.x & 31, wid = threadIdx.x >> 5;
    int total = g_cand_cnt;
    if (total > CAND_CAP) total = CAND_CAP;
    for (int ci = blockIdx.x * 8 + wid; ci < total; ci += gridDim.x * 8) {
        unsigned pc = g_cand[ci];
        int px = pc >> 16, code = pc & 0xFFFF;
        const float* xb = x + (size_t)(px >> 10) * (CDIM * HW) + (px & 1023);
        const float* wr = w + (size_t)code * CDIM;
        float dot = 0.f;
        #pragma unroll
        for (int j = 0; j < 8; j++) {
            int c = l + j * 32;
            dot = fmaf(__ldg(&xb[(size_t)c * HW]), __ldg(&wr[c]), dot);
        }
        #pragma unroll
        for (int o = 16; o > 0; o >>= 1) dot += __shfl_down_sync(0xffffffffu, dot, o);
        if (l == 0) {
            float s = __fadd_rn(__fsub_rn(g_xsq[px], __fmul_rn(2.0f, dot)),
                                __ldg(&g_wsq[code]));
            atomicMin(&g_key[px], packKey(s, (unsigned)code));
        }
    }
}

// ---------------- gather + write outputs (resolves rescued pixels inline) ----
__global__ __launch_bounds__(256) void gather_kernel(const float* __restrict__ w,
                                                     float* __restrict__ out) {
    __shared__ float wsh[32][257];
    __shared__ int idxsh[32];

    const int bh = blockIdx.x;
    const int b  = bh >> 5;
    const int h  = bh & 31;
    const int p0 = bh * 32;
    const int tid = threadIdx.x;

    if (tid < 32) {
        int idx = g_idx[p0 + tid];
        if (idx < 0) idx = (int)(g_key[p0 + tid] & 0xFFFFFFFFULL);
        idxsh[tid] = idx;
        out[2 * BCHW + p0 + tid] = (float)idx;
    }
    __syncthreads();

    for (int j = tid; j < 32 * CDIM; j += 256) {
        int wl = j >> 8, c = j & 255;
        wsh[wl][c] = w[(size_t)idxsh[wl] * CDIM + c];
    }
    __syncthreads();

    const int qbase = b * (CDIM * HW) + h * 32;
    for (int j = tid; j < 32 * CDIM; j += 256) {
        int c = j >> 5, ww = j & 31;
        float v = wsh[ww][c];
        int addr = qbase + c * HW + ww;
        out[addr] = v;
        out[addr + BCHW] = v;
    }
}

extern "C" void kernel_launch(void* const* d_in, const int* in_sizes, int n_in,
                              void* d_out, int out_size) {
    const float* x = (const float*)d_in[0];   // (64, 256, 32, 32) f32
    const float* w = (const float*)d_in[1];   // (1024, 256) f32
    float* out = (float*)d_out;

    cudaFuncSetAttribute(vq_mma, cudaFuncAttributeMaxDynamicSharedMemorySize, SM_TOT);
    cudaFuncSetAttribute(rescue_scan, cudaFuncAttributeMaxDynamicSharedMemorySize, SC_TOT);

    prep_w<<<NCODE, 256>>>(w);
    prep_x<<<NPIX / 256, 256>>>(x);
    vq_mma<<<NPIX / 64, 256, SM_TOT>>>();
    rescue_scan<<<512, 256, SC_TOT>>>();
    rescue_exact<<<256, 256>>>(x, w);
    gather_kernel<<<NPIX / 32, 256>>>(w, out);
}

// round 13
// speedup vs baseline: 1.7627x; 1.0593x over previous
#include <cuda_runtime.h>
#include <cuda_fp16.h>
#include <stdint.h>

#define NCODE 1024
#define CDIM  256
#define NPIX  65536
#define HW    1024
#define BCHW  16777216
#define FLAG_CAP 32768
#define CAND_CAP 131072
#define GAP_THRESH 2.0e-4f

// ---------------- device scratch (no allocations allowed) ----------------
__device__ __half g_xhi[(size_t)NPIX * CDIM];   // 32 MB
__device__ __half g_whi[NCODE * CDIM];
__device__ float g_wsq[NCODE];
__device__ float g_xsq[NPIX];
__device__ float g_bests[NPIX];
__device__ int   g_idx[NPIX];
__device__ unsigned long long g_key[NPIX];
__device__ int   g_flag_cnt;
__device__ int   g_flag_list[FLAG_CAP];
__device__ int   g_cand_cnt;
__device__ unsigned g_cand[CAND_CAP];

__device__ __forceinline__ uint32_t smem_u32(const void* p) {
    uint32_t a;
    asm("{ .reg .u64 t; cvta.to.shared.u64 t, %1; cvt.u32.u64 %0, t; }" : "=r"(a) : "l"(p));
    return a;
}

__device__ __forceinline__ unsigned long long packKey(float s, unsigned idx) {
    unsigned u = __float_as_uint(s);
    u = (u & 0x80000000u) ? ~u : (u | 0x80000000u);
    return (((unsigned long long)u) << 32) | (unsigned long long)idx;
}

__device__ __forceinline__ void cpasync16(uint32_t d, const void* s) {
    asm volatile("cp.async.ca.shared.global [%0], [%1], 16;" :: "r"(d), "l"(s) : "memory");
}

__device__ __forceinline__ void ldsm4(uint32_t* r, uint32_t addr) {
    asm volatile("ldmatrix.sync.aligned.m8n8.x4.shared.b16 {%0,%1,%2,%3}, [%4];"
                 : "=r"(r[0]), "=r"(r[1]), "=r"(r[2]), "=r"(r[3]) : "r"(addr));
}

__device__ __forceinline__ void mma_f16(float* c, const uint32_t* a, const uint32_t* b) {
    asm volatile(
        "mma.sync.aligned.m16n8k16.row.col.f32.f16.f16.f32 "
        "{%0,%1,%2,%3}, {%4,%5,%6,%7}, {%8,%9}, {%0,%1,%2,%3};"
        : "+f"(c[0]), "+f"(c[1]), "+f"(c[2]), "+f"(c[3])
        : "r"(a[0]), "r"(a[1]), "r"(a[2]), "r"(a[3]), "r"(b[0]), "r"(b[1]));
}

// ---------------- prep kernels ----------------
__global__ void prep_w(const float* __restrict__ w) {
    __shared__ float red[8];
    int code = blockIdx.x, t = threadIdx.x;
    if (code == 0 && t == 0) { g_flag_cnt = 0; g_cand_cnt = 0; }
    float v = w[code * CDIM + t];
    g_whi[code * CDIM + t] = __float2half(v);
    float s = v * v;
    #pragma unroll
    for (int o = 16; o > 0; o >>= 1) s += __shfl_down_sync(0xffffffffu, s, o);
    if ((t & 31) == 0) red[t >> 5] = s;
    __syncthreads();
    if (t == 0) {
        g_wsq[code] = ((red[0] + red[1]) + (red[2] + red[3])) +
                      ((red[4] + red[5]) + (red[6] + red[7]));
    }
}

// x (B,C,H,W) f32 -> (pixel, C) fp16 + |x|^2 (xsq chain order identical to R1/R10)
__global__ void prep_x(const float* __restrict__ x) {
    int p = blockIdx.x * 256 + threadIdx.x;
    const float* base = x + (size_t)(p >> 10) * (CDIM * HW) + (p & 1023);
    float s0 = 0.f, s1 = 0.f, s2 = 0.f, s3 = 0.f;
    uint4* dhi = (uint4*)(g_xhi + (size_t)p * CDIM);
    #pragma unroll 8
    for (int c = 0; c < CDIM; c += 8) {
        float v[8];
        #pragma unroll
        for (int i = 0; i < 8; i++) v[i] = base[(c + i) * HW];
        s0 += v[0] * v[0]; s1 += v[1] * v[1]; s2 += v[2] * v[2]; s3 += v[3] * v[3];
        s0 += v[4] * v[4]; s1 += v[5] * v[5]; s2 += v[6] * v[6]; s3 += v[7] * v[7];
        uint32_t hw_[4];
        #pragma unroll
        for (int i = 0; i < 4; i++) {
            __half2 h2 = __floats2half2_rn(v[2 * i], v[2 * i + 1]);
            hw_[i] = *(uint32_t*)&h2;
        }
        dhi[c >> 3] = make_uint4(hw_[0], hw_[1], hw_[2], hw_[3]);
    }
    g_xsq[p] = (s0 + s1) + (s2 + s3);
}

// Generic W-tile stager: 128 codes x 256 fp16 (64KB), 256 threads
__device__ __forceinline__ void stage_wtile_at(uint32_t dstbase, int ct, int tid) {
    int r = tid >> 1, half = tid & 1;
    uint32_t dst = dstbase + (uint32_t)r * 512;
    uint32_t xm = (r & 7) << 4;
    const char* srow = (const char*)(g_whi + (size_t)(ct * 128 + r) * CDIM);
    #pragma unroll
    for (int j = 0; j < 16; j++) {
        uint32_t kb = half * 256 + j * 16;
        cpasync16(dst + (kb ^ xm), srow + kb);
    }
}

// 512-thread W-tile stager
__device__ __forceinline__ void stage_wtile512(uint32_t dstbase, int ct, int tid) {
    int r = tid >> 2, q = tid & 3;
    uint32_t dst = dstbase + (uint32_t)r * 512;
    uint32_t xm = (r & 7) << 4;
    const char* srow = (const char*)(g_whi + (size_t)(ct * 128 + r) * CDIM);
    #pragma unroll
    for (int j = 0; j < 8; j++) {
        uint32_t kb = q * 128 + j * 16;
        cpasync16(dst + (kb ^ xm), srow + kb);
    }
}

// ---------------- fused HMMA GEMM + top-2 argmin (128-px strips, 512 CTAs) ----
#define SM_X   0
#define SM_W   65536
#define SM_RED 196608
#define SM_TOT (196608 + 6144)

__global__ __launch_bounds__(512, 1) void vq_mma() {
    extern __shared__ char smem[];
    uint32_t sb = smem_u32(smem);
    const int tid = threadIdx.x, l = tid & 31, wid = tid >> 5;
    const int mw = wid & 3;        // code-warp: 4 x 32 codes
    const int nw = wid >> 2;       // pixel-warp: 4 x 32 pixels
    const int row0 = blockIdx.x * 128;
    float* s1sh = (float*)(smem + SM_RED);
    int*   i1sh = (int*)(smem + SM_RED + 2048);
    float* s2sh = (float*)(smem + SM_RED + 4096);

    // Stage resident X strip (512B swizzled rows)
    {
        int r = tid >> 2, q = tid & 3;
        const char* shi = (const char*)(g_xhi + (size_t)(row0 + r) * CDIM);
        uint32_t dx = sb + SM_X + (uint32_t)r * 512;
        uint32_t xm = (r & 7) << 4;
        #pragma unroll
        for (int j = 0; j < 8; j++) {
            uint32_t kb = q * 128 + j * 16;
            cpasync16(dx + (kb ^ xm), shi + kb);
        }
    }
    stage_wtile512(sb + SM_W, 0, tid);
    asm volatile("cp.async.commit_group;" ::: "memory");
    stage_wtile512(sb + SM_W + 65536, 1, tid);
    asm volatile("cp.async.commit_group;" ::: "memory");

    float xsqr[8];
    #pragma unroll
    for (int s = 0; s < 8; s++) {
        int px = nw * 32 + (s >> 1) * 8 + (l & 3) * 2 + (s & 1);
        xsqr[s] = g_xsq[row0 + px];
    }

    uint32_t a_row[2], a_x[2];
    #pragma unroll
    for (int tm = 0; tm < 2; tm++) {
        int rA = mw * 32 + tm * 16 + (l & 15);
        a_row[tm] = rA * 512;
        a_x[tm] = (rA & 7) << 4;
    }
    const uint32_t off16a = (l >> 4) * 16;
    uint32_t b_row[2], b_x[2];
    #pragma unroll
    for (int tp = 0; tp < 2; tp++) {
        int rB = nw * 32 + tp * 16 + (l & 7) + ((l >> 4) << 3);
        b_row[tp] = rB * 512;
        b_x[tp] = (rB & 7) << 4;
    }
    const uint32_t off16b = ((l >> 3) & 1) * 16;

    float acc[2][4][4];
    #pragma unroll
    for (int i = 0; i < 2; i++)
        #pragma unroll
        for (int j = 0; j < 4; j++)
            #pragma unroll
            for (int k = 0; k < 4; k++) acc[i][j][k] = 0.f;

    float best_s[8], sec_s[8];
    int best_i[8];
    #pragma unroll
    for (int s = 0; s < 8; s++) { best_s[s] = 3.4e38f; sec_s[s] = 3.4e38f; best_i[s] = 0; }

    for (int ct = 0; ct < 8; ct++) {
        if (ct < 7) asm volatile("cp.async.wait_group 1;" ::: "memory");
        else        asm volatile("cp.async.wait_group 0;" ::: "memory");
        __syncthreads();

        uint32_t bufw = sb + SM_W + (uint32_t)(ct & 1) * 65536;
        #pragma unroll
        for (int kk = 0; kk < 16; kk++) {
            uint32_t a0[4], a1[4];
            uint32_t ca = kk * 32 + off16a;
            ldsm4(a0, bufw + a_row[0] + (ca ^ a_x[0]));
            ldsm4(a1, bufw + a_row[1] + (ca ^ a_x[1]));
            uint32_t kb = kk * 32 + off16b;
            #pragma unroll
            for (int tp = 0; tp < 2; tp++) {
                uint32_t b[4];
                ldsm4(b, sb + SM_X + b_row[tp] + (kb ^ b_x[tp]));
                mma_f16(acc[0][2 * tp],     a0, b);
                mma_f16(acc[0][2 * tp + 1], a0, b + 2);
                mma_f16(acc[1][2 * tp],     a1, b);
                mma_f16(acc[1][2 * tp + 1], a1, b + 2);
            }
        }
        __syncthreads();   // all warps done reading bufw before restage
        if (ct + 2 < 8) {
            stage_wtile512(sb + SM_W + (uint32_t)(ct & 1) * 65536, ct + 2, tid);
            asm volatile("cp.async.commit_group;" ::: "memory");
        }

        // Fold this code tile into running top-2
        {
            int cb = ct * 128 + mw * 32 + (l >> 2);
            float wq0 = __ldg(&g_wsq[cb]);
            float wq1 = __ldg(&g_wsq[cb + 8]);
            float wq2 = __ldg(&g_wsq[cb + 16]);
            float wq3 = __ldg(&g_wsq[cb + 24]);
            #pragma unroll
            for (int tm = 0; tm < 2; tm++) {
                float wlo_ = tm ? wq2 : wq0;
                float whi_ = tm ? wq3 : wq1;
                int c_lo = cb + tm * 16, c_hi = cb + tm * 16 + 8;
                #pragma unroll
                for (int tn = 0; tn < 4; tn++) {
                    #pragma unroll
                    for (int rg = 0; rg < 4; rg++) {
                        int slot = tn * 2 + (rg & 1);
                        float dot = acc[tm][tn][rg];
                        float wq = (rg >> 1) ? whi_ : wlo_;
                        int code = (rg >> 1) ? c_hi : c_lo;
                        float s = __fadd_rn(__fsub_rn(xsqr[slot],
                                                      __fmul_rn(2.0f, dot)), wq);
                        if (s < best_s[slot]) {
                            sec_s[slot] = best_s[slot];
                            best_s[slot] = s; best_i[slot] = code;
                        } else if (s < sec_s[slot]) {
                            sec_s[slot] = s;
                        }
                        acc[tm][tn][rg] = 0.f;
                    }
                }
            }
        }
    }

    // Cross-lane top-2 merge
    #pragma unroll
    for (int s = 0; s < 8; s++) {
        float bs = best_s[s], ss = sec_s[s];
        int bi = best_i[s];
        #pragma unroll
        for (int off = 4; off <= 16; off <<= 1) {
            float ob = __shfl_xor_sync(0xffffffffu, bs, off);
            int   oi = __shfl_xor_sync(0xffffffffu, bi, off);
            float os = __shfl_xor_sync(0xffffffffu, ss, off);
            bool take = (ob < bs) || (ob == bs && oi < bi);
            float losing = take ? bs : ob;
            if (take) { bs = ob; bi = oi; }
            ss = fminf(fminf(ss, os), losing);
        }
        if ((l >> 2) == 0) {
            int px = nw * 32 + (s >> 1) * 8 + (l & 3) * 2 + (s & 1);
            s1sh[mw * 128 + px] = bs;
            i1sh[mw * 128 + px] = bi;
            s2sh[mw * 128 + px] = ss;
        }
    }
    __syncthreads();

    // Cross-warp merge (4 code-warps per pixel); flag near-ties for rescue
    if (tid < 128) {
        float bs = s1sh[tid]; int bi = i1sh[tid]; float ss = s2sh[tid];
        #pragma unroll
        for (int wv = 1; wv < 4; wv++) {
            float ob = s1sh[wv * 128 + tid];
            int   oi = i1sh[wv * 128 + tid];
            float os = s2sh[wv * 128 + tid];
            bool take = (ob < bs) || (ob == bs && oi < bi);
            float losing = take ? bs : ob;
            if (take) { bs = ob; bi = oi; }
            ss = fminf(fminf(ss, os), losing);
        }
        int p = row0 + tid;
        g_bests[p] = bs;
        if (ss - bs < GAP_THRESH) {
            int slot = atomicAdd(&g_flag_cnt, 1);
            if (slot < FLAG_CAP) {
                g_flag_list[slot] = p;
                g_key[p] = ~0ull;
                g_idx[p] = -1;        // gather resolves from g_key
            } else {
                g_idx[p] = bi;
            }
        } else {
            g_idx[p] = bi;
        }
    }
}

// ---------------- rescue scan: approx-rescore flagged px, emit candidates ----
// smem: XS 64KB | W 64KB (single) | pxid 512B
#define SC_X   0
#define SC_W   65536
#define SC_PX  131072
#define SC_TOT (131072 + 512)

__global__ __launch_bounds__(256, 1) void rescue_scan() {
    extern __shared__ char smem[];
    uint32_t sb = smem_u32(smem);
    const int tid = threadIdx.x, l = tid & 31, wid = tid >> 5;
    const int mw = wid & 3, nw = wid >> 2;
    const int split = blockIdx.x & 7;        // code tile (one of 8)
    const int gslot = blockIdx.x >> 3;       // group slot (64)
    int* pxid = (int*)(smem + SC_PX);

    int nflag = g_flag_cnt;
    if (nflag > FLAG_CAP) nflag = FLAG_CAP;
    int ngroups = (nflag + 127) >> 7;
    if (gslot >= ngroups) return;

    stage_wtile_at(sb + SC_W, split, tid);
    asm volatile("cp.async.commit_group;" ::: "memory");

    uint32_t a_row[2], a_x[2];
    #pragma unroll
    for (int tm = 0; tm < 2; tm++) {
        int rA = mw * 32 + tm * 16 + (l & 15);
        a_row[tm] = rA * 512;
        a_x[tm] = (rA & 7) << 4;
    }
    const uint32_t off16a = (l >> 4) * 16;
    uint32_t b_row[4], b_x[4];
    #pragma unroll
    for (int tp = 0; tp < 4; tp++) {
        int rB = nw * 64 + tp * 16 + (l & 7) + ((l >> 4) << 3);
        b_row[tp] = rB * 512;
        b_x[tp] = (rB & 7) << 4;
    }
    const uint32_t off16b = ((l >> 3) & 1) * 16;

    float acc[2][8][4];
    #pragma unroll
    for (int i = 0; i < 2; i++)
        #pragma unroll
        for (int j = 0; j < 8; j++)
            #pragma unroll
            for (int k = 0; k < 4; k++) acc[i][j][k] = 0.f;

    for (int grp = gslot; grp < ngroups; grp += 64) {
        int base = grp * 128;
        __syncthreads();     // previous group done with XS
        if (tid < 128) {
            int fi = base + tid;
            pxid[tid] = g_flag_list[(fi < nflag) ? fi : (nflag - 1)];
        }
        __syncthreads();

        {
            int r = tid >> 1, half = tid & 1;
            const char* shi = (const char*)(g_xhi + (size_t)pxid[r] * CDIM);
            uint32_t dx = sb + SC_X + (uint32_t)r * 512;
            uint32_t xm = (r & 7) << 4;
            #pragma unroll
            for (int j = 0; j < 16; j++) {
                uint32_t kb = half * 256 + j * 16;
                cpasync16(dx + (kb ^ xm), shi + kb);
            }
        }
        asm volatile("cp.async.commit_group;" ::: "memory");

        float xsqr[16], lims[16];
        int pxs[16];
        #pragma unroll
        for (int s = 0; s < 16; s++) {
            int r = nw * 64 + (s >> 1) * 8 + (l & 3) * 2 + (s & 1);
            int p = pxid[r];
            pxs[s] = p;
            xsqr[s] = g_xsq[p];
            lims[s] = g_bests[p] + GAP_THRESH;
        }

        asm volatile("cp.async.wait_group 0;" ::: "memory");
        __syncthreads();

        uint32_t bufw = sb + SC_W;
        #pragma unroll 4
        for (int kk = 0; kk < 16; kk++) {
            uint32_t a0[4], a1[4];
            uint32_t ca = kk * 32 + off16a;
            ldsm4(a0, bufw + a_row[0] + (ca ^ a_x[0]));
            ldsm4(a1, bufw + a_row[1] + (ca ^ a_x[1]));
            uint32_t kb = kk * 32 + off16b;
            #pragma unroll
            for (int tp = 0; tp < 4; tp++) {
                uint32_t b[4];
                ldsm4(b, sb + SC_X + b_row[tp] + (kb ^ b_x[tp]));
                mma_f16(acc[0][2 * tp],     a0, b);
                mma_f16(acc[0][2 * tp + 1], a0, b + 2);
                mma_f16(acc[1][2 * tp],     a1, b);
                mma_f16(acc[1][2 * tp + 1], a1, b + 2);
            }
        }

        int cb = split * 128 + mw * 32 + (l >> 2);
        float wq0 = __ldg(&g_wsq[cb]);
        float wq1 = __ldg(&g_wsq[cb + 8]);
        float wq2 = __ldg(&g_wsq[cb + 16]);
        float wq3 = __ldg(&g_wsq[cb + 24]);
        #pragma unroll
        for (int tm = 0; tm < 2; tm++) {
            float wlo_ = tm ? wq2 : wq0;
            float whi_ = tm ? wq3 : wq1;
            int c_lo = cb + tm * 16, c_hi = cb + tm * 16 + 8;
            #pragma unroll
            for (int tn = 0; tn < 8; tn++) {
                #pragma unroll
                for (int rg = 0; rg < 4; rg++) {
                    int slot = tn * 2 + (rg & 1);
                    float dot = acc[tm][tn][rg];
                    float wq = (rg >> 1) ? whi_ : wlo_;
                    int code = (rg >> 1) ? c_hi : c_lo;
                    float s = __fadd_rn(__fsub_rn(xsqr[slot],
                                                  __fmul_rn(2.0f, dot)), wq);
                    if (s < lims[slot]) {
                        int ci = atomicAdd(&g_cand_cnt, 1);
                        if (ci < CAND_CAP)
                            g_cand[ci] = ((unsigned)pxs[slot] << 16) | (unsigned)code;
                    }
                    acc[tm][tn][rg] = 0.f;
                }
            }
        }
    }
}

// ---------------- exact fp32 scoring of candidates (1 warp each) ----------------
__global__ __launch_bounds__(256) void rescue_exact(const float* __restrict__ x,
                                                    const float* __restrict__ w) {
    const int l = threadIdx.x & 31, wid = threadIdx.x >> 5;
    int total = g_cand_cnt;
    if (total > CAND_CAP) total = CAND_CAP;
    for (int ci = blockIdx.x * 8 + wid; ci < total; ci += gridDim.x * 8) {
        unsigned pc = g_cand[ci];
        int px = pc >> 16, code = pc & 0xFFFF;
        const float* xb = x + (size_t)(px >> 10) * (CDIM * HW) + (px & 1023);
        const float* wr = w + (size_t)code * CDIM;
        float dot = 0.f;
        #pragma unroll
        for (int j = 0; j < 8; j++) {
            int c = l + j * 32;
            dot = fmaf(__ldg(&xb[(size_t)c * HW]), __ldg(&wr[c]), dot);
        }
        #pragma unroll
        for (int o = 16; o > 0; o >>= 1) dot += __shfl_down_sync(0xffffffffu, dot, o);
        if (l == 0) {
            float s = __fadd_rn(__fsub_rn(g_xsq[px], __fmul_rn(2.0f, dot)),
                                __ldg(&g_wsq[code]));
            atomicMin(&g_key[px], packKey(s, (unsigned)code));
        }
    }
}

// ---------------- gather + write outputs (resolves rescued pixels inline) ----
__global__ __launch_bounds__(256) void gather_kernel(const float* __restrict__ w,
                                                     float* __restrict__ out) {
    __shared__ float wsh[32][257];
    __shared__ int idxsh[32];

    const int bh = blockIdx.x;
    const int b  = bh >> 5;
    const int h  = bh & 31;
    const int p0 = bh * 32;
    const int tid = threadIdx.x;

    if (tid < 32) {
        int idx = g_idx[p0 + tid];
        if (idx < 0) idx = (int)(g_key[p0 + tid] & 0xFFFFFFFFULL);
        idxsh[tid] = idx;
        out[2 * BCHW + p0 + tid] = (float)idx;
    }
    __syncthreads();

    for (int j = tid; j < 32 * CDIM; j += 256) {
        int wl = j >> 8, c = j & 255;
        wsh[wl][c] = w[(size_t)idxsh[wl] * CDIM + c];
    }
    __syncthreads();

    const int qbase = b * (CDIM * HW) + h * 32;
    for (int j = tid; j < 32 * CDIM; j += 256) {
        int c = j >> 5, ww = j & 31;
        float v = wsh[ww][c];
        int addr = qbase + c * HW + ww;
        out[addr] = v;
        out[addr + BCHW] = v;
    }
}

extern "C" void kernel_launch(void* const* d_in, const int* in_sizes, int n_in,
                              void* d_out, int out_size) {
    const float* x = (const float*)d_in[0];   // (64, 256, 32, 32) f32
    const float* w = (const float*)d_in[1];   // (1024, 256) f32
    float* out = (float*)d_out;

    cudaFuncSetAttribute(vq_mma, cudaFuncAttributeMaxDynamicSharedMemorySize, SM_TOT);
    cudaFuncSetAttribute(rescue_scan, cudaFuncAttributeMaxDynamicSharedMemorySize, SC_TOT);

    prep_w<<<NCODE, 256>>>(w);
    prep_x<<<NPIX / 256, 256>>>(x);
    vq_mma<<<NPIX / 128, 512, SM_TOT>>>();
    rescue_scan<<<512, 256, SC_TOT>>>();
    rescue_exact<<<128, 256>>>(x, w);
    gather_kernel<<<NPIX / 32, 256>>>(w, out);
}

// round 14
// speedup vs baseline: 2.3947x; 1.3586x over previous
#include <cuda_runtime.h>
#include <cuda_fp16.h>
#include <stdint.h>

#define NCODE 1024
#define CDIM  256
#define NPIX  65536
#define HW    1024
#define BCHW  16777216
#define FLAG_CAP 32768
#define CAND_CAP 131072
#define GAP_THRESH 2.0e-4f
#define NSLOT 37                   // 148 CTAs = 4 quarters x 37 slots
#define NSTRIP 1024                // 64-pixel strips

// ---------------- device scratch (no allocations allowed) ----------------
__device__ __half g_xhi[(size_t)NPIX * CDIM];   // 32 MB
__device__ __half g_whi[NCODE * CDIM];
__device__ float g_wsq[NCODE];
__device__ float g_xsq[NPIX];
__device__ float g_bests[NPIX];
__device__ int   g_idx[NPIX];
__device__ unsigned long long g_key[NPIX];
__device__ int   g_flag_cnt;
__device__ int   g_flag_list[FLAG_CAP];
__device__ int   g_cand_cnt;
__device__ unsigned g_cand[CAND_CAP];
// per-quarter partial top-2, layout [pixel][quarter]
__device__ float g_q1s[NPIX * 4];
__device__ int   g_q1i[NPIX * 4];
__device__ float g_q2s[NPIX * 4];

__device__ __forceinline__ uint32_t smem_u32(const void* p) {
    uint32_t a;
    asm("{ .reg .u64 t; cvta.to.shared.u64 t, %1; cvt.u32.u64 %0, t; }" : "=r"(a) : "l"(p));
    return a;
}

__device__ __forceinline__ unsigned long long packKey(float s, unsigned idx) {
    unsigned u = __float_as_uint(s);
    u = (u & 0x80000000u) ? ~u : (u | 0x80000000u);
    return (((unsigned long long)u) << 32) | (unsigned long long)idx;
}

__device__ __forceinline__ void cpasync16(uint32_t d, const void* s) {
    asm volatile("cp.async.ca.shared.global [%0], [%1], 16;" :: "r"(d), "l"(s) : "memory");
}

__device__ __forceinline__ void ldsm4(uint32_t* r, uint32_t addr) {
    asm volatile("ldmatrix.sync.aligned.m8n8.x4.shared.b16 {%0,%1,%2,%3}, [%4];"
                 : "=r"(r[0]), "=r"(r[1]), "=r"(r[2]), "=r"(r[3]) : "r"(addr));
}

__device__ __forceinline__ void mma_f16(float* c, const uint32_t* a, const uint32_t* b) {
    asm volatile(
        "mma.sync.aligned.m16n8k16.row.col.f32.f16.f16.f32 "
        "{%0,%1,%2,%3}, {%4,%5,%6,%7}, {%8,%9}, {%0,%1,%2,%3};"
        : "+f"(c[0]), "+f"(c[1]), "+f"(c[2]), "+f"(c[3])
        : "r"(a[0]), "r"(a[1]), "r"(a[2]), "r"(a[3]), "r"(b[0]), "r"(b[1]));
}

// ---------------- prep kernels (identical to R13) ----------------
__global__ void prep_w(const float* __restrict__ w) {
    __shared__ float red[8];
    int code = blockIdx.x, t = threadIdx.x;
    if (code == 0 && t == 0) { g_flag_cnt = 0; g_cand_cnt = 0; }
    float v = w[code * CDIM + t];
    g_whi[code * CDIM + t] = __float2half(v);
    float s = v * v;
    #pragma unroll
    for (int o = 16; o > 0; o >>= 1) s += __shfl_down_sync(0xffffffffu, s, o);
    if ((t & 31) == 0) red[t >> 5] = s;
    __syncthreads();
    if (t == 0) {
        g_wsq[code] = ((red[0] + red[1]) + (red[2] + red[3])) +
                      ((red[4] + red[5]) + (red[6] + red[7]));
    }
}

__global__ void prep_x(const float* __restrict__ x) {
    int p = blockIdx.x * 256 + threadIdx.x;
    const float* base = x + (size_t)(p >> 10) * (CDIM * HW) + (p & 1023);
    float s0 = 0.f, s1 = 0.f, s2 = 0.f, s3 = 0.f;
    uint4* dhi = (uint4*)(g_xhi + (size_t)p * CDIM);
    #pragma unroll 8
    for (int c = 0; c < CDIM; c += 8) {
        float v[8];
        #pragma unroll
        for (int i = 0; i < 8; i++) v[i] = base[(c + i) * HW];
        s0 += v[0] * v[0]; s1 += v[1] * v[1]; s2 += v[2] * v[2]; s3 += v[3] * v[3];
        s0 += v[4] * v[4]; s1 += v[5] * v[5]; s2 += v[6] * v[6]; s3 += v[7] * v[7];
        uint32_t hw_[4];
        #pragma unroll
        for (int i = 0; i < 4; i++) {
            __half2 h2 = __floats2half2_rn(v[2 * i], v[2 * i + 1]);
            hw_[i] = *(uint32_t*)&h2;
        }
        dhi[c >> 3] = make_uint4(hw_[0], hw_[1], hw_[2], hw_[3]);
    }
    g_xsq[p] = (s0 + s1) + (s2 + s3);
}

// 128-code W-tile stager (64KB), 256 threads — used by rescue_scan
__device__ __forceinline__ void stage_wtile_at(uint32_t dstbase, int ct, int tid) {
    int r = tid >> 1, half = tid & 1;
    uint32_t dst = dstbase + (uint32_t)r * 512;
    uint32_t xm = (r & 7) << 4;
    const char* srow = (const char*)(g_whi + (size_t)(ct * 128 + r) * CDIM);
    #pragma unroll
    for (int j = 0; j < 16; j++) {
        uint32_t kb = half * 256 + j * 16;
        cpasync16(dst + (kb ^ xm), srow + kb);
    }
}

// 512-thread 128-code W-tile stager
__device__ __forceinline__ void stage_wtile512(uint32_t dstbase, int ct, int tid) {
    int r = tid >> 2, q = tid & 3;
    uint32_t dst = dstbase + (uint32_t)r * 512;
    uint32_t xm = (r & 7) << 4;
    const char* srow = (const char*)(g_whi + (size_t)(ct * 128 + r) * CDIM);
    #pragma unroll
    for (int j = 0; j < 8; j++) {
        uint32_t kb = q * 128 + j * 16;
        cpasync16(dst + (kb ^ xm), srow + kb);
    }
}

// 512-thread 64-pixel X-strip stager (32KB)
__device__ __forceinline__ void stage_xstrip(uint32_t dstbase, int strip, int tid) {
    int r = tid >> 3, o = tid & 7;
    const char* srow = (const char*)(g_xhi + (size_t)(strip * 64 + r) * CDIM);
    uint32_t dst = dstbase + (uint32_t)r * 512;
    uint32_t xm = (r & 7) << 4;
    #pragma unroll
    for (int j = 0; j < 4; j++) {
        uint32_t kb = o * 64 + j * 16;
        cpasync16(dst + (kb ^ xm), srow + kb);
    }
}

// ---------------- persistent quarter-resident HMMA GEMM ----------------
// smem: W 128KB (resident quarter) | X 2x32KB | red 6KB
#define SM_W   0
#define SM_X   131072
#define SM_RED 196608
#define SM_TOT (196608 + 6144)

__global__ __launch_bounds__(512, 1) void vq_mma() {
    extern __shared__ char smem[];
    uint32_t sb = smem_u32(smem);
    const int tid = threadIdx.x, l = tid & 31, wid = tid >> 5;
    const int cw = wid & 7;        // code-warp: 8 x 32 codes (full 256-code quarter)
    const int pw = wid >> 3;       // pixel-warp: 2 x 32 pixels
    const int qid = blockIdx.x & 3;
    const int slot = blockIdx.x >> 2;   // 0..36
    float* s1sh = (float*)(smem + SM_RED);
    int*   i1sh = (int*)(smem + SM_RED + 2048);
    float* s2sh = (float*)(smem + SM_RED + 4096);

    // Stage resident W quarter (256 codes = 2 tiles), then X prefetch pipeline
    stage_wtile512(sb + SM_W, qid * 2, tid);
    stage_wtile512(sb + SM_W + 65536, qid * 2 + 1, tid);
    asm volatile("cp.async.commit_group;" ::: "memory");
    stage_xstrip(sb + SM_X, slot, tid);
    asm volatile("cp.async.commit_group;" ::: "memory");
    if (slot + NSLOT < NSTRIP) {
        stage_xstrip(sb + SM_X + 32768, slot + NSLOT, tid);
        asm volatile("cp.async.commit_group;" ::: "memory");
    }

    // A (codes): row within the 256-row resident W region
    uint32_t a_row[2], a_x[2];
    #pragma unroll
    for (int tm = 0; tm < 2; tm++) {
        int rA = cw * 32 + tm * 16 + (l & 15);
        a_row[tm] = rA * 512;
        a_x[tm] = (rA & 7) << 4;
    }
    const uint32_t off16a = (l >> 4) * 16;
    // B (pixels): 2 x 16-px fragments within the 64-row X strip
    uint32_t b_row[2], b_x[2];
    #pragma unroll
    for (int tp = 0; tp < 2; tp++) {
        int rB = pw * 32 + tp * 16 + (l & 7) + ((l >> 4) << 3);
        b_row[tp] = rB * 512;
        b_x[tp] = (rB & 7) << 4;
    }
    const uint32_t off16b = ((l >> 3) & 1) * 16;

    const int cb = qid * 256 + cw * 32 + (l >> 2);
    const float wq0 = __ldg(&g_wsq[cb]);
    const float wq1 = __ldg(&g_wsq[cb + 8]);
    const float wq2 = __ldg(&g_wsq[cb + 16]);
    const float wq3 = __ldg(&g_wsq[cb + 24]);

    float acc[2][4][4];
    #pragma unroll
    for (int i = 0; i < 2; i++)
        #pragma unroll
        for (int j = 0; j < 4; j++)
            #pragma unroll
            for (int k = 0; k < 4; k++) acc[i][j][k] = 0.f;

    int buf = 0;
    for (int s = slot; s < NSTRIP; s += NSLOT, buf ^= 1) {
        bool more = (s + NSLOT < NSTRIP);
        if (more) asm volatile("cp.async.wait_group 1;" ::: "memory");
        else      asm volatile("cp.async.wait_group 0;" ::: "memory");
        __syncthreads();   // X(s) visible; also fences previous strip's red reads

        const int row0 = s * 64;
        float xsqr[8];
        #pragma unroll
        for (int sl = 0; sl < 8; sl++) {
            int px = pw * 32 + (sl >> 1) * 8 + (l & 3) * 2 + (sl & 1);
            xsqr[sl] = g_xsq[row0 + px];
        }

        uint32_t bufx = sb + SM_X + (uint32_t)buf * 32768;
        #pragma unroll
        for (int kk = 0; kk < 16; kk++) {
            uint32_t a0[4], a1[4];
            uint32_t ca = kk * 32 + off16a;
            ldsm4(a0, sb + SM_W + a_row[0] + (ca ^ a_x[0]));
            ldsm4(a1, sb + SM_W + a_row[1] + (ca ^ a_x[1]));
            uint32_t kb = kk * 32 + off16b;
            #pragma unroll
            for (int tp = 0; tp < 2; tp++) {
                uint32_t b[4];
                ldsm4(b, bufx + b_row[tp] + (kb ^ b_x[tp]));
                mma_f16(acc[0][2 * tp],     a0, b);
                mma_f16(acc[0][2 * tp + 1], a0, b + 2);
                mma_f16(acc[1][2 * tp],     a1, b);
                mma_f16(acc[1][2 * tp + 1], a1, b + 2);
            }
        }
        __syncthreads();   // all warps done reading bufx before restage
        if (s + 2 * NSLOT < NSTRIP) {
            stage_xstrip(bufx, s + 2 * NSLOT, tid);
            asm volatile("cp.async.commit_group;" ::: "memory");
        }

        // Fold all 256 quarter codes (same per-(px,code) chain as R13 / scan)
        float best_s[8], sec_s[8];
        int best_i[8];
        #pragma unroll
        for (int sl = 0; sl < 8; sl++) { best_s[sl] = 3.4e38f; sec_s[sl] = 3.4e38f; best_i[sl] = 0; }
        #pragma unroll
        for (int tm = 0; tm < 2; tm++) {
            float wlo_ = tm ? wq2 : wq0;
            float whi_ = tm ? wq3 : wq1;
            int c_lo = cb + tm * 16, c_hi = cb + tm * 16 + 8;
            #pragma unroll
            for (int tn = 0; tn < 4; tn++) {
                #pragma unroll
                for (int rg = 0; rg < 4; rg++) {
                    int sl = tn * 2 + (rg & 1);
                    float dot = acc[tm][tn][rg];
                    float wq = (rg >> 1) ? whi_ : wlo_;
                    int code = (rg >> 1) ? c_hi : c_lo;
                    float sc = __fadd_rn(__fsub_rn(xsqr[sl],
                                                   __fmul_rn(2.0f, dot)), wq);
                    if (sc < best_s[sl]) {
                        sec_s[sl] = best_s[sl];
                        best_s[sl] = sc; best_i[sl] = code;
                    } else if (sc < sec_s[sl]) {
                        sec_s[sl] = sc;
                    }
                    acc[tm][tn][rg] = 0.f;
                }
            }
        }

        // Cross-lane top-2 merge (8 lanes per pixel slot set)
        #pragma unroll
        for (int sl = 0; sl < 8; sl++) {
            float bs = best_s[sl], ss = sec_s[sl];
            int bi = best_i[sl];
            #pragma unroll
            for (int off = 4; off <= 16; off <<= 1) {
                float ob = __shfl_xor_sync(0xffffffffu, bs, off);
                int   oi = __shfl_xor_sync(0xffffffffu, bi, off);
                float os = __shfl_xor_sync(0xffffffffu, ss, off);
                bool take = (ob < bs) || (ob == bs && oi < bi);
                float losing = take ? bs : ob;
                if (take) { bs = ob; bi = oi; }
                ss = fminf(fminf(ss, os), losing);
            }
            if ((l >> 2) == 0) {
                int px = pw * 32 + (sl >> 1) * 8 + (l & 3) * 2 + (sl & 1);
                s1sh[cw * 64 + px] = bs;
                i1sh[cw * 64 + px] = bi;
                s2sh[cw * 64 + px] = ss;
            }
        }
        __syncthreads();

        // Cross-warp merge (8 code-warps); write per-quarter partials
        if (tid < 64) {
            float bs = s1sh[tid]; int bi = i1sh[tid]; float ss = s2sh[tid];
            #pragma unroll
            for (int wv = 1; wv < 8; wv++) {
                float ob = s1sh[wv * 64 + tid];
                int   oi = i1sh[wv * 64 + tid];
                float os = s2sh[wv * 64 + tid];
                bool take = (ob < bs) || (ob == bs && oi < bi);
                float losing = take ? bs : ob;
                if (take) { bs = ob; bi = oi; }
                ss = fminf(fminf(ss, os), losing);
            }
            int p = row0 + tid;
            g_q1s[p * 4 + qid] = bs;
            g_q1i[p * 4 + qid] = bi;
            g_q2s[p * 4 + qid] = ss;
        }
    }
}

// ---------------- cross-quarter merge + flagging ----------------
__global__ __launch_bounds__(256) void merge_quarters() {
    int p = blockIdx.x * 256 + threadIdx.x;
    float bs = g_q1s[p * 4]; int bi = g_q1i[p * 4]; float ss = g_q2s[p * 4];
    #pragma unroll
    for (int q = 1; q < 4; q++) {
        float ob = g_q1s[p * 4 + q];
        int   oi = g_q1i[p * 4 + q];
        float os = g_q2s[p * 4 + q];
        bool take = (ob < bs) || (ob == bs && oi < bi);
        float losing = take ? bs : ob;
        if (take) { bs = ob; bi = oi; }
        ss = fminf(fminf(ss, os), losing);
    }
    g_bests[p] = bs;
    if (ss - bs < GAP_THRESH) {
        int slot = atomicAdd(&g_flag_cnt, 1);
        if (slot < FLAG_CAP) {
            g_flag_list[slot] = p;
            g_key[p] = ~0ull;
            g_idx[p] = -1;
        } else {
            g_idx[p] = bi;
        }
    } else {
        g_idx[p] = bi;
    }
}

// ---------------- rescue scan (identical to R13) ----------------
// smem: XS 64KB | W 64KB (single) | pxid 512B
#define SC_X   0
#define SC_W   65536
#define SC_PX  131072
#define SC_TOT (131072 + 512)

__global__ __launch_bounds__(256, 1) void rescue_scan() {
    extern __shared__ char smem[];
    uint32_t sb = smem_u32(smem);
    const int tid = threadIdx.x, l = tid & 31, wid = tid >> 5;
    const int mw = wid & 3, nw = wid >> 2;
    const int split = blockIdx.x & 7;
    const int gslot = blockIdx.x >> 3;
    int* pxid = (int*)(smem + SC_PX);

    int nflag = g_flag_cnt;
    if (nflag > FLAG_CAP) nflag = FLAG_CAP;
    int ngroups = (nflag + 127) >> 7;
    if (gslot >= ngroups) return;

    stage_wtile_at(sb + SC_W, split, tid);
    asm volatile("cp.async.commit_group;" ::: "memory");

    uint32_t a_row[2], a_x[2];
    #pragma unroll
    for (int tm = 0; tm < 2; tm++) {
        int rA = mw * 32 + tm * 16 + (l & 15);
        a_row[tm] = rA * 512;
        a_x[tm] = (rA & 7) << 4;
    }
    const uint32_t off16a = (l >> 4) * 16;
    uint32_t b_row[4], b_x[4];
    #pragma unroll
    for (int tp = 0; tp < 4; tp++) {
        int rB = nw * 64 + tp * 16 + (l & 7) + ((l >> 4) << 3);
        b_row[tp] = rB * 512;
        b_x[tp] = (rB & 7) << 4;
    }
    const uint32_t off16b = ((l >> 3) & 1) * 16;

    float acc[2][8][4];
    #pragma unroll
    for (int i = 0; i < 2; i++)
        #pragma unroll
        for (int j = 0; j < 8; j++)
            #pragma unroll
            for (int k = 0; k < 4; k++) acc[i][j][k] = 0.f;

    for (int grp = gslot; grp < ngroups; grp += 64) {
        int base = grp * 128;
        __syncthreads();
        if (tid < 128) {
            int fi = base + tid;
            pxid[tid] = g_flag_list[(fi < nflag) ? fi : (nflag - 1)];
        }
        __syncthreads();

        {
            int r = tid >> 1, half = tid & 1;
            const char* shi = (const char*)(g_xhi + (size_t)pxid[r] * CDIM);
            uint32_t dx = sb + SC_X + (uint32_t)r * 512;
            uint32_t xm = (r & 7) << 4;
            #pragma unroll
            for (int j = 0; j < 16; j++) {
                uint32_t kb = half * 256 + j * 16;
                cpasync16(dx + (kb ^ xm), shi + kb);
            }
        }
        asm volatile("cp.async.commit_group;" ::: "memory");

        float xsqr[16], lims[16];
        int pxs[16];
        #pragma unroll
        for (int s = 0; s < 16; s++) {
            int r = nw * 64 + (s >> 1) * 8 + (l & 3) * 2 + (s & 1);
            int p = pxid[r];
            pxs[s] = p;
            xsqr[s] = g_xsq[p];
            lims[s] = g_bests[p] + GAP_THRESH;
        }

        asm volatile("cp.async.wait_group 0;" ::: "memory");
        __syncthreads();

        uint32_t bufw = sb + SC_W;
        #pragma unroll 4
        for (int kk = 0; kk < 16; kk++) {
            uint32_t a0[4], a1[4];
            uint32_t ca = kk * 32 + off16a;
            ldsm4(a0, bufw + a_row[0] + (ca ^ a_x[0]));
            ldsm4(a1, bufw + a_row[1] + (ca ^ a_x[1]));
            uint32_t kb = kk * 32 + off16b;
            #pragma unroll
            for (int tp = 0; tp < 4; tp++) {
                uint32_t b[4];
                ldsm4(b, sb + SC_X + b_row[tp] + (kb ^ b_x[tp]));
                mma_f16(acc[0][2 * tp],     a0, b);
                mma_f16(acc[0][2 * tp + 1], a0, b + 2);
                mma_f16(acc[1][2 * tp],     a1, b);
                mma_f16(acc[1][2 * tp + 1], a1, b + 2);
            }
        }

        int cb = split * 128 + mw * 32 + (l >> 2);
        float wq0 = __ldg(&g_wsq[cb]);
        float wq1 = __ldg(&g_wsq[cb + 8]);
        float wq2 = __ldg(&g_wsq[cb + 16]);
        float wq3 = __ldg(&g_wsq[cb + 24]);
        #pragma unroll
        for (int tm = 0; tm < 2; tm++) {
            float wlo_ = tm ? wq2 : wq0;
            float whi_ = tm ? wq3 : wq1;
            int c_lo = cb + tm * 16, c_hi = cb + tm * 16 + 8;
            #pragma unroll
            for (int tn = 0; tn < 8; tn++) {
                #pragma unroll
                for (int rg = 0; rg < 4; rg++) {
                    int slot = tn * 2 + (rg & 1);
                    float dot = acc[tm][tn][rg];
                    float wq = (rg >> 1) ? whi_ : wlo_;
                    int code = (rg >> 1) ? c_hi : c_lo;
                    float s = __fadd_rn(__fsub_rn(xsqr[slot],
                                                  __fmul_rn(2.0f, dot)), wq);
                    if (s < lims[slot]) {
                        int ci = atomicAdd(&g_cand_cnt, 1);
                        if (ci < CAND_CAP)
                            g_cand[ci] = ((unsigned)pxs[slot] << 16) | (unsigned)code;
                    }
                    acc[tm][tn][rg] = 0.f;
                }
            }
        }
    }
}

// ---------------- exact fp32 scoring of candidates (1 warp each) ----------------
__global__ __launch_bounds__(256) void rescue_exact(const float* __restrict__ x,
                                                    const float* __restrict__ w) {
    const int l = threadIdx.x & 31, wid = threadIdx.x >> 5;
    int total = g_cand_cnt;
    if (total > CAND_CAP) total = CAND_CAP;
    for (int ci = blockIdx.x * 8 + wid; ci < total; ci += gridDim.x * 8) {
        unsigned pc = g_cand[ci];
        int px = pc >> 16, code = pc & 0xFFFF;
        const float* xb = x + (size_t)(px >> 10) * (CDIM * HW) + (px & 1023);
        const float* wr = w + (size_t)code * CDIM;
        float dot = 0.f;
        #pragma unroll
        for (int j = 0; j < 8; j++) {
            int c = l + j * 32;
            dot = fmaf(__ldg(&xb[(size_t)c * HW]), __ldg(&wr[c]), dot);
        }
        #pragma unroll
        for (int o = 16; o > 0; o >>= 1) dot += __shfl_down_sync(0xffffffffu, dot, o);
        if (l == 0) {
            float s = __fadd_rn(__fsub_rn(g_xsq[px], __fmul_rn(2.0f, dot)),
                                __ldg(&g_wsq[code]));
            atomicMin(&g_key[px], packKey(s, (unsigned)code));
        }
    }
}

// ---------------- gather + write outputs (resolves rescued pixels inline) ----
__global__ __launch_bounds__(256) void gather_kernel(const float* __restrict__ w,
                                                     float* __restrict__ out) {
    __shared__ float wsh[32][257];
    __shared__ int idxsh[32];

    const int bh = blockIdx.x;
    const int b  = bh >> 5;
    const int h  = bh & 31;
    const int p0 = bh * 32;
    const int tid = threadIdx.x;

    if (tid < 32) {
        int idx = g_idx[p0 + tid];
        if (idx < 0) idx = (int)(g_key[p0 + tid] & 0xFFFFFFFFULL);
        idxsh[tid] = idx;
        out[2 * BCHW + p0 + tid] = (float)idx;
    }
    __syncthreads();

    for (int j = tid; j < 32 * CDIM; j += 256) {
        int wl = j >> 8, c = j & 255;
        wsh[wl][c] = w[(size_t)idxsh[wl] * CDIM + c];
    }
    __syncthreads();

    const int qbase = b * (CDIM * HW) + h * 32;
    for (int j = tid; j < 32 * CDIM; j += 256) {
        int c = j >> 5, ww = j & 31;
        float v = wsh[ww][c];
        int addr = qbase + c * HW + ww;
        out[addr] = v;
        out[addr + BCHW] = v;
    }
}

extern "C" void kernel_launch(void* const* d_in, const int* in_sizes, int n_in,
                              void* d_out, int out_size) {
    const float* x = (const float*)d_in[0];   // (64, 256, 32, 32) f32
    const float* w = (const float*)d_in[1];   // (1024, 256) f32
    float* out = (float*)d_out;

    cudaFuncSetAttribute(vq_mma, cudaFuncAttributeMaxDynamicSharedMemorySize, SM_TOT);
    cudaFuncSetAttribute(rescue_scan, cudaFuncAttributeMaxDynamicSharedMemorySize, SC_TOT);

    prep_w<<<NCODE, 256>>>(w);
    prep_x<<<NPIX / 256, 256>>>(x);
    vq_mma<<<4 * NSLOT, 512, SM_TOT>>>();        // 148 persistent CTAs
    merge_quarters<<<NPIX / 256, 256>>>();
    rescue_scan<<<512, 256, SC_TOT>>>();
    rescue_exact<<<128, 256>>>(x, w);
    gather_kernel<<<NPIX / 32, 256>>>(w, out);
}